// round 3
// baseline (speedup 1.0000x reference)
#include <cuda_runtime.h>
#include <math.h>

#define BB  2
#define TT  2048
#define DD  1024
#define HH  16
#define DKK 64
#define BH  (BB*HH)

// Scratch (allocation-free): q,k,v in [B*H, T, 64]; o in [B, T, D] (heads concatenated)
__device__ float g_q[(size_t)BH * TT * DKK];
__device__ float g_k[(size_t)BH * TT * DKK];
__device__ float g_v[(size_t)BH * TT * DKK];
__device__ float g_o[(size_t)BB * TT * DD];

__device__ __forceinline__ float fast_exp2(float x) {
    float y;
    asm("ex2.approx.ftz.f32 %0, %1;" : "=f"(y) : "f"(x));
    return y;
}

// ---------------------------------------------------------------------------
// Kernel 1: per-head QKV projection.
// grid = (T/64, B*H), 256 threads. Tile: 64 tokens x 64 dims.
// Micro: 4x4 per thread, three accumulators (q,k,v) share one x-tile read.
// Dynamic smem: xs[64][65] + wq/wk/wv[64][65] = 66,560 B
// ---------------------------------------------------------------------------
__global__ __launch_bounds__(256) void qkv_kernel(
    const float* __restrict__ x,  const float* __restrict__ Wq,
    const float* __restrict__ Wk, const float* __restrict__ Wv)
{
    extern __shared__ float sm[];
    float* xs = sm;                 // [64][65], xs[t][d]
    float* wq = sm + 64 * 65;       // [64][65], wq[kout][d]
    float* wk = wq + 64 * 65;
    float* wv = wk + 64 * 65;

    const int bh = blockIdx.y;
    const int b  = bh / HH, h = bh % HH;
    const int t0 = blockIdx.x * 64;
    const int tid = threadIdx.x;
    const int tx = tid & 15, ty = tid >> 4;

    {
        const int c4 = tid & 15;   // float4 column group
        const int r0 = tid >> 4;   // base row
        const float* xp  = x  + ((size_t)(b * TT + t0)) * DD + h * DKK;
        const float* wqp = Wq + (size_t)h * DKK * DKK;
        const float* wkp = Wk + (size_t)h * DKK * DKK;
        const float* wvp = Wv + (size_t)h * DKK * DKK;
        #pragma unroll
        for (int r = 0; r < 4; r++) {
            const int row = r0 + r * 16;
            float4 vx = *(const float4*)(xp  + (size_t)row * DD + c4 * 4);
            float4 vq = *(const float4*)(wqp + row * 64 + c4 * 4);
            float4 vk = *(const float4*)(wkp + row * 64 + c4 * 4);
            float4 vv = *(const float4*)(wvp + row * 64 + c4 * 4);
            const int o = row * 65 + c4 * 4;
            xs[o+0]=vx.x; xs[o+1]=vx.y; xs[o+2]=vx.z; xs[o+3]=vx.w;
            wq[o+0]=vq.x; wq[o+1]=vq.y; wq[o+2]=vq.z; wq[o+3]=vq.w;
            wk[o+0]=vk.x; wk[o+1]=vk.y; wk[o+2]=vk.z; wk[o+3]=vk.w;
            wv[o+0]=vv.x; wv[o+1]=vv.y; wv[o+2]=vv.z; wv[o+3]=vv.w;
        }
    }
    __syncthreads();

    float aq[4][4], ak[4][4], av[4][4];
    #pragma unroll
    for (int i = 0; i < 4; i++)
        #pragma unroll
        for (int j = 0; j < 4; j++) { aq[i][j]=0.f; ak[i][j]=0.f; av[i][j]=0.f; }

    #pragma unroll 8
    for (int kk = 0; kk < 64; kk++) {
        float a[4], bq[4], bk2[4], bv2[4];
        #pragma unroll
        for (int i = 0; i < 4; i++) a[i] = xs[(ty * 4 + i) * 65 + kk];
        #pragma unroll
        for (int j = 0; j < 4; j++) {
            const int col = (tx + 16 * j) * 65 + kk;
            bq[j] = wq[col]; bk2[j] = wk[col]; bv2[j] = wv[col];
        }
        #pragma unroll
        for (int i = 0; i < 4; i++)
            #pragma unroll
            for (int j = 0; j < 4; j++) {
                aq[i][j] += a[i] * bq[j];
                ak[i][j] += a[i] * bk2[j];
                av[i][j] += a[i] * bv2[j];
            }
    }

    float* qo = g_q + ((size_t)bh * TT + t0) * DKK;
    float* ko = g_k + ((size_t)bh * TT + t0) * DKK;
    float* vo = g_v + ((size_t)bh * TT + t0) * DKK;
    #pragma unroll
    for (int i = 0; i < 4; i++) {
        const int ro = (ty * 4 + i) * DKK;
        #pragma unroll
        for (int j = 0; j < 4; j++) {
            const int c = tx + 16 * j;
            qo[ro + c] = aq[i][j];
            ko[ro + c] = ak[i][j];
            vo[ro + c] = av[i][j];
        }
    }
}

// ---------------------------------------------------------------------------
// Kernel 2: causal flash attention, fp32.
// grid = (T/128, B*H), 256 threads. Q-tile 128, K-tile 64, dk 64.
// Micro 8x4. Heavy CTAs (large q0) run first.
// Dynamic smem: Qs[128][65] + Ks[64][65] + Vs[64][65] + Ps[128][65] = 99,840 B
// ---------------------------------------------------------------------------
__global__ __launch_bounds__(256) void attn_kernel()
{
    extern __shared__ float sm[];
    float* Qs = sm;                      // [128][65]
    float* Ks = Qs + 128 * 65;           // [64][65]
    float* Vs = Ks + 64 * 65;            // [64][65]
    float* Ps = Vs + 64 * 65;            // [128][65]

    const int bh = blockIdx.y;
    const int q0 = (gridDim.x - 1 - blockIdx.x) * 128;  // heavy blocks first
    const int tid = threadIdx.x;
    const int tx = tid & 15, ty = tid >> 4;

    const float* Qg = g_q + ((size_t)bh * TT + q0) * DKK;
    const float* Kg = g_k + (size_t)bh * TT * DKK;
    const float* Vg = g_v + (size_t)bh * TT * DKK;

    {   // load Q tile: 128x64 = 32 floats / thread
        const int c4 = tid & 15, r0 = tid >> 4;
        #pragma unroll
        for (int r = 0; r < 8; r++) {
            const int row = r0 + r * 16;
            float4 v4 = *(const float4*)(Qg + (size_t)row * DKK + c4 * 4);
            const int o = row * 65 + c4 * 4;
            Qs[o+0]=v4.x; Qs[o+1]=v4.y; Qs[o+2]=v4.z; Qs[o+3]=v4.w;
        }
    }

    float Oa[8][4], m[8], l[8];
    #pragma unroll
    for (int i = 0; i < 8; i++) {
        m[i] = -1e30f; l[i] = 0.f;
        #pragma unroll
        for (int j = 0; j < 4; j++) Oa[i][j] = 0.f;
    }

    const float l2s = 0.18033688011112042f;  // (1/sqrt(64)) * log2(e)
    const int ntiles = q0 / 64 + 2;

    for (int kt = 0; kt < ntiles; kt++) {
        const int k0 = kt * 64;
        __syncthreads();   // previous PV done before K/V overwrite (no-op first iter)
        {   // load K,V tiles (64x64 each): 16 floats each / thread
            const int c4 = tid & 15, r0 = tid >> 4;
            #pragma unroll
            for (int r = 0; r < 4; r++) {
                const int row = r0 + r * 16;
                float4 vk = *(const float4*)(Kg + (size_t)(k0 + row) * DKK + c4 * 4);
                float4 vv = *(const float4*)(Vg + (size_t)(k0 + row) * DKK + c4 * 4);
                const int o = row * 65 + c4 * 4;
                Ks[o+0]=vk.x; Ks[o+1]=vk.y; Ks[o+2]=vk.z; Ks[o+3]=vk.w;
                Vs[o+0]=vv.x; Vs[o+1]=vv.y; Vs[o+2]=vv.z; Vs[o+3]=vv.w;
            }
        }
        __syncthreads();

        // S = Q K^T  (8x4 per thread)
        float s[8][4];
        #pragma unroll
        for (int i = 0; i < 8; i++)
            #pragma unroll
            for (int j = 0; j < 4; j++) s[i][j] = 0.f;

        #pragma unroll 8
        for (int d = 0; d < 64; d++) {
            float a[8], bb[4];
            #pragma unroll
            for (int i = 0; i < 8; i++) a[i] = Qs[(ty * 8 + i) * 65 + d];
            #pragma unroll
            for (int j = 0; j < 4; j++) bb[j] = Ks[(tx + 16 * j) * 65 + d];
            #pragma unroll
            for (int i = 0; i < 8; i++)
                #pragma unroll
                for (int j = 0; j < 4; j++) s[i][j] += a[i] * bb[j];
        }

        // causal mask (only on the two diagonal tiles)
        if (k0 + 63 > q0) {
            #pragma unroll
            for (int i = 0; i < 8; i++) {
                const int qq = q0 + ty * 8 + i;
                #pragma unroll
                for (int j = 0; j < 4; j++)
                    if (k0 + tx + 16 * j > qq) s[i][j] = -1e30f;
            }
        }

        // online softmax update + P -> smem
        #pragma unroll
        for (int i = 0; i < 8; i++) {
            float rm = s[i][0];
            #pragma unroll
            for (int j = 1; j < 4; j++) rm = fmaxf(rm, s[i][j]);
            #pragma unroll
            for (int off = 8; off > 0; off >>= 1)
                rm = fmaxf(rm, __shfl_xor_sync(0xffffffffu, rm, off));
            const float mn = fmaxf(m[i], rm);
            const float alpha = fast_exp2((m[i] - mn) * l2s);
            m[i] = mn;
            float rs = 0.f;
            #pragma unroll
            for (int j = 0; j < 4; j++) {
                const float p = fast_exp2((s[i][j] - mn) * l2s);
                s[i][j] = p;
                rs += p;
            }
            #pragma unroll
            for (int off = 8; off > 0; off >>= 1)
                rs += __shfl_xor_sync(0xffffffffu, rs, off);
            l[i] = l[i] * alpha + rs;
            #pragma unroll
            for (int j = 0; j < 4; j++) Oa[i][j] *= alpha;
            const int prow = (ty * 8 + i) * 65;
            #pragma unroll
            for (int j = 0; j < 4; j++) Ps[prow + tx + 16 * j] = s[i][j];
        }
        __syncthreads();

        // O += P V
        #pragma unroll 8
        for (int k = 0; k < 64; k++) {
            float a[8], bb[4];
            #pragma unroll
            for (int i = 0; i < 8; i++) a[i] = Ps[(ty * 8 + i) * 65 + k];
            #pragma unroll
            for (int j = 0; j < 4; j++) bb[j] = Vs[k * 65 + tx + 16 * j];
            #pragma unroll
            for (int i = 0; i < 8; i++)
                #pragma unroll
                for (int j = 0; j < 4; j++) Oa[i][j] += a[i] * bb[j];
        }
    }

    // normalize and store concat-heads layout: o[b, q, h*64 + c]
    const int b = bh >> 4, h = bh & 15;
    float* Og = g_o + ((size_t)(b * TT + q0)) * DD + h * DKK;
    #pragma unroll
    for (int i = 0; i < 8; i++) {
        const float inv = 1.0f / l[i];
        #pragma unroll
        for (int j = 0; j < 4; j++)
            Og[(size_t)(ty * 8 + i) * DD + tx + 16 * j] = Oa[i][j] * inv;
    }
}

// ---------------------------------------------------------------------------
// Kernel 3: output projection y = o @ Wp^T + bp   (4096 x 1024 x 1024)
// grid = (D/128, B*T/128), 256 threads, BK=32, micro 8x8.
// Static smem: 2 * 128*33*4 = 33,792 B
// ---------------------------------------------------------------------------
__global__ __launch_bounds__(256) void proj_kernel(
    const float* __restrict__ Wp, const float* __restrict__ bp,
    float* __restrict__ y)
{
    __shared__ float Os[128 * 33];
    __shared__ float Ws[128 * 33];

    const int j0 = blockIdx.x * 128;   // output columns
    const int r0 = blockIdx.y * 128;   // rows (B*T)
    const int tid = threadIdx.x;
    const int tx = tid & 15, ty = tid >> 4;

    float acc[8][8];
    #pragma unroll
    for (int i = 0; i < 8; i++)
        #pragma unroll
        for (int j = 0; j < 8; j++) acc[i][j] = 0.f;

    for (int kc = 0; kc < DD; kc += 32) {
        __syncthreads();
        {   // load 128x32 of o and of Wp
            const int c4 = tid & 7, rb = tid >> 3;
            #pragma unroll
            for (int r = 0; r < 4; r++) {
                const int row = rb + r * 32;
                float4 vo = *(const float4*)(g_o + (size_t)(r0 + row) * DD + kc + c4 * 4);
                float4 vw = *(const float4*)(Wp  + (size_t)(j0 + row) * DD + kc + c4 * 4);
                const int o = row * 33 + c4 * 4;
                Os[o+0]=vo.x; Os[o+1]=vo.y; Os[o+2]=vo.z; Os[o+3]=vo.w;
                Ws[o+0]=vw.x; Ws[o+1]=vw.y; Ws[o+2]=vw.z; Ws[o+3]=vw.w;
            }
        }
        __syncthreads();

        #pragma unroll 8
        for (int kk = 0; kk < 32; kk++) {
            float a[8], bw[8];
            #pragma unroll
            for (int i = 0; i < 8; i++) a[i] = Os[(ty * 8 + i) * 33 + kk];
            #pragma unroll
            for (int j = 0; j < 8; j++) bw[j] = Ws[(tx + 16 * j) * 33 + kk];
            #pragma unroll
            for (int i = 0; i < 8; i++)
                #pragma unroll
                for (int j = 0; j < 8; j++) acc[i][j] += a[i] * bw[j];
        }
    }

    float bj[8];
    #pragma unroll
    for (int j = 0; j < 8; j++) bj[j] = bp[j0 + tx + 16 * j];

    #pragma unroll
    for (int i = 0; i < 8; i++) {
        float* yr = y + (size_t)(r0 + ty * 8 + i) * DD + j0;
        #pragma unroll
        for (int j = 0; j < 8; j++) yr[tx + 16 * j] = acc[i][j] + bj[j];
    }
}

// ---------------------------------------------------------------------------
#define QKV_SMEM  (4 * 64 * 65 * (int)sizeof(float))                    // 66,560
#define ATTN_SMEM ((2 * 128 * 65 + 2 * 64 * 65) * (int)sizeof(float))   // 99,840

extern "C" void kernel_launch(void* const* d_in, const int* in_sizes, int n_in,
                              void* d_out, int out_size)
{
    const float* x  = (const float*)d_in[0];
    const float* Wq = (const float*)d_in[1];
    const float* Wk = (const float*)d_in[2];
    const float* Wv = (const float*)d_in[3];
    const float* Wp = (const float*)d_in[4];
    const float* bp = (const float*)d_in[5];
    float* y = (float*)d_out;

    cudaFuncSetAttribute(qkv_kernel,  cudaFuncAttributeMaxDynamicSharedMemorySize, QKV_SMEM);
    cudaFuncSetAttribute(attn_kernel, cudaFuncAttributeMaxDynamicSharedMemorySize, ATTN_SMEM);

    qkv_kernel<<<dim3(TT / 64, BH), 256, QKV_SMEM>>>(x, Wq, Wk, Wv);
    attn_kernel<<<dim3(TT / 128, BH), 256, ATTN_SMEM>>>();
    proj_kernel<<<dim3(DD / 128, (BB * TT) / 128), 256>>>(Wp, bp, y);
}

// round 5
// speedup vs baseline: 2.5731x; 2.5731x over previous
#include <cuda_runtime.h>
#include <math.h>
#include <stdint.h>

#define BB  2
#define TT  2048
#define DD  1024
#define HH  16
#define DKK 64
#define BH  (BB*HH)

// Scratch (allocation-free): q,k,v in [B*H, T, 64]; o in [B, T, D] (heads concatenated)
__device__ float g_q[(size_t)BH * TT * DKK];
__device__ float g_k[(size_t)BH * TT * DKK];
__device__ float g_v[(size_t)BH * TT * DKK];
__device__ float g_o[(size_t)BB * TT * DD];

__device__ __forceinline__ float fast_exp2(float x) {
    float y;
    asm("ex2.approx.ftz.f32 %0, %1;" : "=f"(y) : "f"(x));
    return y;
}

__device__ __forceinline__ uint32_t f2tf32(float x) {
    uint32_t r;
    asm("cvt.rna.tf32.f32 %0, %1;" : "=r"(r) : "f"(x));
    return r;
}

// D(16x8,f32) += A(16x8,tf32) * B(8x8,tf32)   row.col
__device__ __forceinline__ void mma_tf32(
    float& c0, float& c1, float& c2, float& c3,
    uint32_t a0, uint32_t a1, uint32_t a2, uint32_t a3,
    uint32_t b0, uint32_t b1)
{
    asm volatile(
        "mma.sync.aligned.m16n8k8.row.col.f32.tf32.tf32.f32 "
        "{%0,%1,%2,%3}, {%4,%5,%6,%7}, {%8,%9}, {%0,%1,%2,%3};"
        : "+f"(c0), "+f"(c1), "+f"(c2), "+f"(c3)
        : "r"(a0), "r"(a1), "r"(a2), "r"(a3), "r"(b0), "r"(b1));
}

// ---------------------------------------------------------------------------
// Kernel 1: per-head QKV projection (fp32 FFMA — already at its roofline).
// grid = (T/64, B*H), 256 threads. Tile 64x64, micro 4x4, shared x-tile.
// ---------------------------------------------------------------------------
__global__ __launch_bounds__(256) void qkv_kernel(
    const float* __restrict__ x,  const float* __restrict__ Wq,
    const float* __restrict__ Wk, const float* __restrict__ Wv)
{
    extern __shared__ float sm[];
    float* xs = sm;                 // [64][65]
    float* wq = sm + 64 * 65;
    float* wk = wq + 64 * 65;
    float* wv = wk + 64 * 65;

    const int bh = blockIdx.y;
    const int b  = bh / HH, h = bh % HH;
    const int t0 = blockIdx.x * 64;
    const int tid = threadIdx.x;
    const int tx = tid & 15, ty = tid >> 4;

    {
        const int c4 = tid & 15;
        const int r0 = tid >> 4;
        const float* xp  = x  + ((size_t)(b * TT + t0)) * DD + h * DKK;
        const float* wqp = Wq + (size_t)h * DKK * DKK;
        const float* wkp = Wk + (size_t)h * DKK * DKK;
        const float* wvp = Wv + (size_t)h * DKK * DKK;
        #pragma unroll
        for (int r = 0; r < 4; r++) {
            const int row = r0 + r * 16;
            float4 vx = *(const float4*)(xp  + (size_t)row * DD + c4 * 4);
            float4 vq = *(const float4*)(wqp + row * 64 + c4 * 4);
            float4 vk = *(const float4*)(wkp + row * 64 + c4 * 4);
            float4 vv = *(const float4*)(wvp + row * 64 + c4 * 4);
            const int o = row * 65 + c4 * 4;
            xs[o+0]=vx.x; xs[o+1]=vx.y; xs[o+2]=vx.z; xs[o+3]=vx.w;
            wq[o+0]=vq.x; wq[o+1]=vq.y; wq[o+2]=vq.z; wq[o+3]=vq.w;
            wk[o+0]=vk.x; wk[o+1]=vk.y; wk[o+2]=vk.z; wk[o+3]=vk.w;
            wv[o+0]=vv.x; wv[o+1]=vv.y; wv[o+2]=vv.z; wv[o+3]=vv.w;
        }
    }
    __syncthreads();

    float aq[4][4], ak[4][4], av[4][4];
    #pragma unroll
    for (int i = 0; i < 4; i++)
        #pragma unroll
        for (int j = 0; j < 4; j++) { aq[i][j]=0.f; ak[i][j]=0.f; av[i][j]=0.f; }

    #pragma unroll 8
    for (int kk = 0; kk < 64; kk++) {
        float a[4], bq[4], bk2[4], bv2[4];
        #pragma unroll
        for (int i = 0; i < 4; i++) a[i] = xs[(ty * 4 + i) * 65 + kk];
        #pragma unroll
        for (int j = 0; j < 4; j++) {
            const int col = (tx + 16 * j) * 65 + kk;
            bq[j] = wq[col]; bk2[j] = wk[col]; bv2[j] = wv[col];
        }
        #pragma unroll
        for (int i = 0; i < 4; i++)
            #pragma unroll
            for (int j = 0; j < 4; j++) {
                aq[i][j] += a[i] * bq[j];
                ak[i][j] += a[i] * bk2[j];
                av[i][j] += a[i] * bv2[j];
            }
    }

    float* qo = g_q + ((size_t)bh * TT + t0) * DKK;
    float* ko = g_k + ((size_t)bh * TT + t0) * DKK;
    float* vo = g_v + ((size_t)bh * TT + t0) * DKK;
    #pragma unroll
    for (int i = 0; i < 4; i++) {
        const int ro = (ty * 4 + i) * DKK;
        #pragma unroll
        for (int j = 0; j < 4; j++) {
            const int c = tx + 16 * j;
            qo[ro + c] = aq[i][j];
            ko[ro + c] = ak[i][j];
            vo[ro + c] = av[i][j];
        }
    }
}

// ---------------------------------------------------------------------------
// Kernel 2: causal flash attention, TF32 tensor cores.
// grid = (T/128, B*H), 256 threads = 8 warps. Q-tile 128, K-tile 64.
// Each warp owns 16 Q-rows x full 64 K-cols -> softmax is warp-private.
// Smem pitches: Q/K/P pitch 68 (A/B frag LDS conflict-free: bank=4g+tig),
//               V pitch 72 (B frag conflict-free: bank=8tig+g).
// Dynamic smem: (128*68 + 64*68 + 64*72 + 128*68)*4 = 105,472 B
// ---------------------------------------------------------------------------
__global__ __launch_bounds__(256, 1) void attn_kernel()
{
    extern __shared__ float sm[];
    float* Qs = sm;                       // [128][68] tf32 bits
    float* Ks = Qs + 128 * 68;            // [64][68]
    float* Vs = Ks + 64 * 68;             // [64][72]
    float* Ps = Vs + 64 * 72;             // [128][68]
    uint32_t* Qu = (uint32_t*)Qs;
    uint32_t* Ku = (uint32_t*)Ks;
    uint32_t* Vu = (uint32_t*)Vs;
    uint32_t* Pu = (uint32_t*)Ps;

    const int bh  = blockIdx.y;
    const int q0  = (gridDim.x - 1 - blockIdx.x) * 128;  // heavy blocks first
    const int tid = threadIdx.x;
    const int wid = tid >> 5, lane = tid & 31;
    const int g   = lane >> 2, tig = lane & 3;
    const int wrow = wid * 16;                 // this warp's Q-row base in tile
    const int ar0  = (wrow + g) * 68;          // A-frag row offsets (words)
    const int ar1  = (wrow + g + 8) * 68;

    const float* Qg = g_q + ((size_t)bh * TT + q0) * DKK;
    const float* Kg = g_k + (size_t)bh * TT * DKK;
    const float* Vg = g_v + (size_t)bh * TT * DKK;

    // stage Q tile (tf32-rounded)
    {
        const int c4 = tid & 15, r0 = tid >> 4;
        #pragma unroll
        for (int r = 0; r < 8; r++) {
            const int row = r0 + r * 16;
            float4 v = *(const float4*)(Qg + (size_t)row * DKK + c4 * 4);
            uint4 u = { f2tf32(v.x), f2tf32(v.y), f2tf32(v.z), f2tf32(v.w) };
            *(uint4*)&Qu[row * 68 + c4 * 4] = u;
        }
    }

    float o[8][4];
    #pragma unroll
    for (int nb = 0; nb < 8; nb++)
        #pragma unroll
        for (int c = 0; c < 4; c++) o[nb][c] = 0.f;
    float mrow[2] = { -1e30f, -1e30f };
    float lrow[2] = { 0.f, 0.f };

    const float l2s = 0.18033688011112042f;  // (1/sqrt(64)) * log2(e)
    const int ntiles = q0 / 64 + 2;

    for (int kt = 0; kt < ntiles; kt++) {
        const int k0t = kt * 64;
        __syncthreads();   // all warps done reading previous K/V
        {   // stage K,V tiles (tf32-rounded)
            const int c4 = tid & 15, r0 = tid >> 4;
            #pragma unroll
            for (int r = 0; r < 4; r++) {
                const int row = r0 + r * 16;
                float4 vk = *(const float4*)(Kg + (size_t)(k0t + row) * DKK + c4 * 4);
                float4 vv = *(const float4*)(Vg + (size_t)(k0t + row) * DKK + c4 * 4);
                uint4 uk = { f2tf32(vk.x), f2tf32(vk.y), f2tf32(vk.z), f2tf32(vk.w) };
                uint4 uv = { f2tf32(vv.x), f2tf32(vv.y), f2tf32(vv.z), f2tf32(vv.w) };
                *(uint4*)&Ku[row * 68 + c4 * 4] = uk;
                *(uint4*)&Vu[row * 72 + c4 * 4] = uv;
            }
        }
        __syncthreads();

        // S = Q K^T : warp 16x64, 8 n-blocks x 8 k-steps of m16n8k8
        float sA[8][4];
        #pragma unroll
        for (int nb = 0; nb < 8; nb++)
            #pragma unroll
            for (int c = 0; c < 4; c++) sA[nb][c] = 0.f;

        #pragma unroll
        for (int k0 = 0; k0 < 64; k0 += 8) {
            const uint32_t a0 = Qu[ar0 + k0 + tig];
            const uint32_t a1 = Qu[ar1 + k0 + tig];
            const uint32_t a2 = Qu[ar0 + k0 + tig + 4];
            const uint32_t a3 = Qu[ar1 + k0 + tig + 4];
            #pragma unroll
            for (int nb = 0; nb < 8; nb++) {
                const int br = (nb * 8 + g) * 68 + k0 + tig;
                mma_tf32(sA[nb][0], sA[nb][1], sA[nb][2], sA[nb][3],
                         a0, a1, a2, a3, Ku[br], Ku[br + 4]);
            }
        }

        // per-row-slot online softmax (rows are warp-private)
        #pragma unroll
        for (int rs = 0; rs < 2; rs++) {
            const int qrow = q0 + wrow + g + 8 * rs;
            if (k0t + 63 > qrow) {   // causal mask (diagonal tiles only)
                #pragma unroll
                for (int nb = 0; nb < 8; nb++) {
                    const int c0 = k0t + nb * 8 + 2 * tig;
                    if (c0     > qrow) sA[nb][2*rs]     = -1e30f;
                    if (c0 + 1 > qrow) sA[nb][2*rs + 1] = -1e30f;
                }
            }
            float rm = -1e30f;
            #pragma unroll
            for (int nb = 0; nb < 8; nb++)
                rm = fmaxf(rm, fmaxf(sA[nb][2*rs], sA[nb][2*rs+1]));
            rm = fmaxf(rm, __shfl_xor_sync(0xffffffffu, rm, 1));
            rm = fmaxf(rm, __shfl_xor_sync(0xffffffffu, rm, 2));
            const float mn = fmaxf(mrow[rs], rm);
            const float alpha = fast_exp2((mrow[rs] - mn) * l2s);
            mrow[rs] = mn;
            float rsum = 0.f;
            #pragma unroll
            for (int nb = 0; nb < 8; nb++) {
                float p0 = fast_exp2((sA[nb][2*rs]   - mn) * l2s);
                float p1 = fast_exp2((sA[nb][2*rs+1] - mn) * l2s);
                sA[nb][2*rs] = p0; sA[nb][2*rs+1] = p1;
                rsum += p0 + p1;
            }
            rsum += __shfl_xor_sync(0xffffffffu, rsum, 1);
            rsum += __shfl_xor_sync(0xffffffffu, rsum, 2);
            lrow[rs] = lrow[rs] * alpha + rsum;
            #pragma unroll
            for (int nb = 0; nb < 8; nb++) {
                o[nb][2*rs]   *= alpha;
                o[nb][2*rs+1] *= alpha;
            }
            // P -> smem (tf32), warp-private rows
            const int prow = (wrow + g + 8 * rs) * 68;
            #pragma unroll
            for (int nb = 0; nb < 8; nb++) {
                uint2 pv = { f2tf32(sA[nb][2*rs]), f2tf32(sA[nb][2*rs+1]) };
                *(uint2*)&Pu[prow + nb * 8 + 2 * tig] = pv;
            }
        }
        __syncwarp();   // P STS visible to whole warp before A-frag reload

        // O += P V : 8 n-blocks x 8 k-steps
        #pragma unroll
        for (int k0 = 0; k0 < 64; k0 += 8) {
            const uint32_t a0 = Pu[ar0 + k0 + tig];
            const uint32_t a1 = Pu[ar1 + k0 + tig];
            const uint32_t a2 = Pu[ar0 + k0 + tig + 4];
            const uint32_t a3 = Pu[ar1 + k0 + tig + 4];
            const int vb0 = (k0 + tig) * 72 + g;
            const int vb1 = (k0 + tig + 4) * 72 + g;
            #pragma unroll
            for (int nb = 0; nb < 8; nb++) {
                mma_tf32(o[nb][0], o[nb][1], o[nb][2], o[nb][3],
                         a0, a1, a2, a3, Vu[vb0 + nb * 8], Vu[vb1 + nb * 8]);
            }
        }
    }

    // normalize and store concat-heads layout: o[b, q, h*64 + c]
    const int b = bh >> 4, h = bh & 15;
    float* Og = g_o + ((size_t)(b * TT + q0)) * DD + h * DKK;
    #pragma unroll
    for (int rs = 0; rs < 2; rs++) {
        const float inv = 1.0f / lrow[rs];
        float* orow = Og + (size_t)(wrow + g + 8 * rs) * DD;
        #pragma unroll
        for (int nb = 0; nb < 8; nb++) {
            float2 v = { o[nb][2*rs] * inv, o[nb][2*rs+1] * inv };
            *(float2*)(orow + nb * 8 + 2 * tig) = v;
        }
    }
}

// ---------------------------------------------------------------------------
// Kernel 3: output projection y = o @ Wp^T + bp (4096x1024x1024), TF32 mma.
// grid = (D/128, B*T/128), 256 threads = 8 warps (4M x 2N), warp 32x64, BK=32.
// Smem pitch 36 -> conflict-free fragment LDS. Static smem 2*128*36*4 = 36,864 B
// ---------------------------------------------------------------------------
__global__ __launch_bounds__(256) void proj_kernel(
    const float* __restrict__ Wp, const float* __restrict__ bp,
    float* __restrict__ y)
{
    __shared__ float Osm[128 * 36];
    __shared__ float Wsm[128 * 36];
    uint32_t* Ou = (uint32_t*)Osm;
    uint32_t* Wu = (uint32_t*)Wsm;

    const int j0 = blockIdx.x * 128;
    const int r0 = blockIdx.y * 128;
    const int tid = threadIdx.x;
    const int wid = tid >> 5, lane = tid & 31;
    const int g = lane >> 2, tig = lane & 3;
    const int wm = wid & 3, wn = wid >> 2;

    float acc[2][8][4];
    #pragma unroll
    for (int mf = 0; mf < 2; mf++)
        #pragma unroll
        for (int nb = 0; nb < 8; nb++)
            #pragma unroll
            for (int c = 0; c < 4; c++) acc[mf][nb][c] = 0.f;

    for (int kc = 0; kc < DD; kc += 32) {
        __syncthreads();
        {   // stage 128x32 of o and of Wp (tf32-rounded)
            const int c4 = tid & 7, rb = tid >> 3;
            #pragma unroll
            for (int r = 0; r < 4; r++) {
                const int row = rb + 32 * r;
                float4 vo = *(const float4*)(g_o + (size_t)(r0 + row) * DD + kc + c4 * 4);
                float4 vw = *(const float4*)(Wp  + (size_t)(j0 + row) * DD + kc + c4 * 4);
                uint4 uo = { f2tf32(vo.x), f2tf32(vo.y), f2tf32(vo.z), f2tf32(vo.w) };
                uint4 uw = { f2tf32(vw.x), f2tf32(vw.y), f2tf32(vw.z), f2tf32(vw.w) };
                *(uint4*)&Ou[row * 36 + c4 * 4] = uo;
                *(uint4*)&Wu[row * 36 + c4 * 4] = uw;
            }
        }
        __syncthreads();

        #pragma unroll
        for (int k8 = 0; k8 < 4; k8++) {
            const int kk = k8 * 8;
            uint32_t a[2][4];
            #pragma unroll
            for (int mf = 0; mf < 2; mf++) {
                const int ar = (wm * 32 + mf * 16 + g) * 36 + kk + tig;
                a[mf][0] = Ou[ar];
                a[mf][1] = Ou[ar + 8 * 36];
                a[mf][2] = Ou[ar + 4];
                a[mf][3] = Ou[ar + 8 * 36 + 4];
            }
            #pragma unroll
            for (int nb = 0; nb < 8; nb++) {
                const int br = (wn * 64 + nb * 8 + g) * 36 + kk + tig;
                const uint32_t b0 = Wu[br], b1 = Wu[br + 4];
                mma_tf32(acc[0][nb][0], acc[0][nb][1], acc[0][nb][2], acc[0][nb][3],
                         a[0][0], a[0][1], a[0][2], a[0][3], b0, b1);
                mma_tf32(acc[1][nb][0], acc[1][nb][1], acc[1][nb][2], acc[1][nb][3],
                         a[1][0], a[1][1], a[1][2], a[1][3], b0, b1);
            }
        }
    }

    #pragma unroll
    for (int mf = 0; mf < 2; mf++)
        #pragma unroll
        for (int rs = 0; rs < 2; rs++) {
            const int row = r0 + wm * 32 + mf * 16 + g + 8 * rs;
            float* yr = y + (size_t)row * DD + j0 + wn * 64;
            const float* br = bp + j0 + wn * 64;
            #pragma unroll
            for (int nb = 0; nb < 8; nb++) {
                const int c = nb * 8 + 2 * tig;
                float2 v = { acc[mf][nb][2*rs]   + br[c],
                             acc[mf][nb][2*rs+1] + br[c + 1] };
                *(float2*)(yr + c) = v;
            }
        }
}

// ---------------------------------------------------------------------------
#define QKV_SMEM  (4 * 64 * 65 * (int)sizeof(float))                           // 66,560
#define ATTN_SMEM ((128*68 + 64*68 + 64*72 + 128*68) * (int)sizeof(float))     // 105,472

extern "C" void kernel_launch(void* const* d_in, const int* in_sizes, int n_in,
                              void* d_out, int out_size)
{
    const float* x  = (const float*)d_in[0];
    const float* Wq = (const float*)d_in[1];
    const float* Wk = (const float*)d_in[2];
    const float* Wv = (const float*)d_in[3];
    const float* Wp = (const float*)d_in[4];
    const float* bp = (const float*)d_in[5];
    float* y = (float*)d_out;

    cudaFuncSetAttribute(qkv_kernel,  cudaFuncAttributeMaxDynamicSharedMemorySize, QKV_SMEM);
    cudaFuncSetAttribute(attn_kernel, cudaFuncAttributeMaxDynamicSharedMemorySize, ATTN_SMEM);

    qkv_kernel<<<dim3(TT / 64, BH), 256, QKV_SMEM>>>(x, Wq, Wk, Wv);
    attn_kernel<<<dim3(TT / 128, BH), 256, ATTN_SMEM>>>();
    proj_kernel<<<dim3(DD / 128, (BB * TT) / 128), 256>>>(Wp, bp, y);
}

// round 6
// speedup vs baseline: 3.3718x; 1.3104x over previous
#include <cuda_runtime.h>
#include <math.h>
#include <stdint.h>

#define BB  2
#define TT  2048
#define DD  1024
#define HH  16
#define DKK 64
#define BH  (BB*HH)

// Scratch (allocation-free): q,k,v in [B*H, T, 64]; o in [B, T, D] (heads concatenated)
__device__ float g_q[(size_t)BH * TT * DKK];
__device__ float g_k[(size_t)BH * TT * DKK];
__device__ float g_v[(size_t)BH * TT * DKK];
__device__ float g_o[(size_t)BB * TT * DD];

__device__ __forceinline__ float fast_exp2(float x) {
    float y;
    asm("ex2.approx.ftz.f32 %0, %1;" : "=f"(y) : "f"(x));
    return y;
}

__device__ __forceinline__ uint32_t f2tf32(float x) {
    uint32_t r;
    asm("cvt.rna.tf32.f32 %0, %1;" : "=r"(r) : "f"(x));
    return r;
}

// D(16x8,f32) += A(16x8,tf32) * B(8x8,tf32)   row.col
__device__ __forceinline__ void mma_tf32(
    float& c0, float& c1, float& c2, float& c3,
    uint32_t a0, uint32_t a1, uint32_t a2, uint32_t a3,
    uint32_t b0, uint32_t b1)
{
    asm volatile(
        "mma.sync.aligned.m16n8k8.row.col.f32.tf32.tf32.f32 "
        "{%0,%1,%2,%3}, {%4,%5,%6,%7}, {%8,%9}, {%0,%1,%2,%3};"
        : "+f"(c0), "+f"(c1), "+f"(c2), "+f"(c3)
        : "r"(a0), "r"(a1), "r"(a2), "r"(a3), "r"(b0), "r"(b1));
}

// ---------------------------------------------------------------------------
// Kernel 1: per-head QKV projection, TF32 tensor cores.
// grid = (T/128, B*H), 256 threads = 8 warps. Tile: 128 tokens x (3x64) out.
// Each warp owns 16 token-rows; one x A-fragment set feeds q,k,v MMAs.
// Dynamic smem: (128*68 + 3*64*68)*4 = 87,040 B
// ---------------------------------------------------------------------------
__global__ __launch_bounds__(256) void qkv_kernel(
    const float* __restrict__ x,  const float* __restrict__ Wq,
    const float* __restrict__ Wk, const float* __restrict__ Wv)
{
    extern __shared__ float sm[];
    uint32_t* Xu  = (uint32_t*)sm;        // [128][68]
    uint32_t* Wqu = Xu  + 128 * 68;       // [64][68]
    uint32_t* Wku = Wqu + 64 * 68;
    uint32_t* Wvu = Wku + 64 * 68;

    const int bh = blockIdx.y;
    const int b  = bh >> 4, h = bh & 15;
    const int t0 = blockIdx.x * 128;
    const int tid = threadIdx.x;
    const int wid = tid >> 5, lane = tid & 31;
    const int g = lane >> 2, tig = lane & 3;
    const int wrow = wid * 16;

    {   // stage x tile (128x64) and the three 64x64 weights, tf32-rounded
        const int c4 = tid & 15, r0 = tid >> 4;
        const float* xp = x + ((size_t)(b * TT + t0)) * DD + h * DKK;
        #pragma unroll
        for (int r = 0; r < 8; r++) {
            const int row = r0 + r * 16;
            float4 v = *(const float4*)(xp + (size_t)row * DD + c4 * 4);
            uint4 u = { f2tf32(v.x), f2tf32(v.y), f2tf32(v.z), f2tf32(v.w) };
            *(uint4*)&Xu[row * 68 + c4 * 4] = u;
        }
        const float* wqp = Wq + (size_t)h * DKK * DKK;
        const float* wkp = Wk + (size_t)h * DKK * DKK;
        const float* wvp = Wv + (size_t)h * DKK * DKK;
        #pragma unroll
        for (int r = 0; r < 4; r++) {
            const int row = r0 + r * 16;
            float4 vq = *(const float4*)(wqp + row * 64 + c4 * 4);
            float4 vk = *(const float4*)(wkp + row * 64 + c4 * 4);
            float4 vv = *(const float4*)(wvp + row * 64 + c4 * 4);
            uint4 uq = { f2tf32(vq.x), f2tf32(vq.y), f2tf32(vq.z), f2tf32(vq.w) };
            uint4 uk = { f2tf32(vk.x), f2tf32(vk.y), f2tf32(vk.z), f2tf32(vk.w) };
            uint4 uv = { f2tf32(vv.x), f2tf32(vv.y), f2tf32(vv.z), f2tf32(vv.w) };
            *(uint4*)&Wqu[row * 68 + c4 * 4] = uq;
            *(uint4*)&Wku[row * 68 + c4 * 4] = uk;
            *(uint4*)&Wvu[row * 68 + c4 * 4] = uv;
        }
    }
    __syncthreads();

    float aq[8][4], ak[8][4], av[8][4];
    #pragma unroll
    for (int nb = 0; nb < 8; nb++)
        #pragma unroll
        for (int c = 0; c < 4; c++) { aq[nb][c]=0.f; ak[nb][c]=0.f; av[nb][c]=0.f; }

    const int ar0 = (wrow + g) * 68;
    const int ar1 = (wrow + g + 8) * 68;

    #pragma unroll
    for (int k0 = 0; k0 < 64; k0 += 8) {
        const uint32_t a0 = Xu[ar0 + k0 + tig];
        const uint32_t a1 = Xu[ar1 + k0 + tig];
        const uint32_t a2 = Xu[ar0 + k0 + tig + 4];
        const uint32_t a3 = Xu[ar1 + k0 + tig + 4];
        #pragma unroll
        for (int nb = 0; nb < 8; nb++) {
            const int br = (nb * 8 + g) * 68 + k0 + tig;
            mma_tf32(aq[nb][0], aq[nb][1], aq[nb][2], aq[nb][3],
                     a0, a1, a2, a3, Wqu[br], Wqu[br + 4]);
            mma_tf32(ak[nb][0], ak[nb][1], ak[nb][2], ak[nb][3],
                     a0, a1, a2, a3, Wku[br], Wku[br + 4]);
            mma_tf32(av[nb][0], av[nb][1], av[nb][2], av[nb][3],
                     a0, a1, a2, a3, Wvu[br], Wvu[br + 4]);
        }
    }

    #pragma unroll
    for (int rs = 0; rs < 2; rs++) {
        const size_t row = (size_t)bh * TT + t0 + wrow + g + 8 * rs;
        float* qo = g_q + row * DKK;
        float* ko = g_k + row * DKK;
        float* vo = g_v + row * DKK;
        #pragma unroll
        for (int nb = 0; nb < 8; nb++) {
            const int c = nb * 8 + 2 * tig;
            float2 vq2 = { aq[nb][2*rs], aq[nb][2*rs+1] };
            float2 vk2 = { ak[nb][2*rs], ak[nb][2*rs+1] };
            float2 vv2 = { av[nb][2*rs], av[nb][2*rs+1] };
            *(float2*)(qo + c) = vq2;
            *(float2*)(ko + c) = vk2;
            *(float2*)(vo + c) = vv2;
        }
    }
}

// ---------------------------------------------------------------------------
// Kernel 2: causal flash attention, TF32, double-buffered K/V.
// grid = (T/128, B*H), 256 threads = 8 warps. Q-tile 128, K-tile 64.
// Per tile: prefetch next K/V to regs -> 1 syncthreads -> compute -> STS other buf.
// Dynamic smem: (128*68 + 2*64*68 + 2*64*72 + 128*68)*4 = 141,312 B
// ---------------------------------------------------------------------------
__global__ __launch_bounds__(256, 1) void attn_kernel()
{
    extern __shared__ float sm[];
    uint32_t* Qu = (uint32_t*)sm;             // [128][68]
    uint32_t* Kb = Qu + 128 * 68;             // [2][64][68]
    uint32_t* Vb = Kb + 2 * 64 * 68;          // [2][64][72]
    uint32_t* Pu = Vb + 2 * 64 * 72;          // [128][68]

    const int bh  = blockIdx.y;
    const int q0  = (gridDim.x - 1 - blockIdx.x) * 128;  // heavy blocks first
    const int tid = threadIdx.x;
    const int wid = tid >> 5, lane = tid & 31;
    const int g   = lane >> 2, tig = lane & 3;
    const int wrow = wid * 16;
    const int ar0  = (wrow + g) * 68;
    const int ar1  = (wrow + g + 8) * 68;
    const int c4 = tid & 15, sr0 = tid >> 4;

    const float* Qg = g_q + ((size_t)bh * TT + q0) * DKK;
    const float* Kg = g_k + (size_t)bh * TT * DKK;
    const float* Vg = g_v + (size_t)bh * TT * DKK;

    // stage Q tile
    #pragma unroll
    for (int r = 0; r < 8; r++) {
        const int row = sr0 + r * 16;
        float4 v = *(const float4*)(Qg + (size_t)row * DKK + c4 * 4);
        uint4 u = { f2tf32(v.x), f2tf32(v.y), f2tf32(v.z), f2tf32(v.w) };
        *(uint4*)&Qu[row * 68 + c4 * 4] = u;
    }
    // stage K/V tile 0 into buffer 0
    #pragma unroll
    for (int r = 0; r < 4; r++) {
        const int row = sr0 + r * 16;
        float4 vk = *(const float4*)(Kg + (size_t)row * DKK + c4 * 4);
        float4 vv = *(const float4*)(Vg + (size_t)row * DKK + c4 * 4);
        uint4 uk = { f2tf32(vk.x), f2tf32(vk.y), f2tf32(vk.z), f2tf32(vk.w) };
        uint4 uv = { f2tf32(vv.x), f2tf32(vv.y), f2tf32(vv.z), f2tf32(vv.w) };
        *(uint4*)&Kb[row * 68 + c4 * 4] = uk;
        *(uint4*)&Vb[row * 72 + c4 * 4] = uv;
    }

    float o[8][4];
    #pragma unroll
    for (int nb = 0; nb < 8; nb++)
        #pragma unroll
        for (int c = 0; c < 4; c++) o[nb][c] = 0.f;
    float mrow[2] = { -1e30f, -1e30f };
    float lrow[2] = { 0.f, 0.f };

    const float l2s = 0.18033688011112042f;  // (1/sqrt(64)) * log2(e)
    const int ntiles = q0 / 64 + 2;

    for (int kt = 0; kt < ntiles; kt++) {
        // prefetch next K/V tile into registers (clamped; discarded on last iter)
        const int knext = min((kt + 1) * 64, TT - 64);
        float4 rk[4], rv[4];
        #pragma unroll
        for (int r = 0; r < 4; r++) {
            const int row = knext + sr0 + r * 16;
            rk[r] = *(const float4*)(Kg + (size_t)row * DKK + c4 * 4);
            rv[r] = *(const float4*)(Vg + (size_t)row * DKK + c4 * 4);
        }

        __syncthreads();   // current buffer's STS visible; prev reads of other buf done
        const uint32_t* Ku = Kb + (kt & 1) * 64 * 68;
        const uint32_t* Vu = Vb + (kt & 1) * 64 * 72;
        const int k0t = kt * 64;

        // S = Q K^T : warp 16x64
        float sA[8][4];
        #pragma unroll
        for (int nb = 0; nb < 8; nb++)
            #pragma unroll
            for (int c = 0; c < 4; c++) sA[nb][c] = 0.f;

        #pragma unroll
        for (int k0 = 0; k0 < 64; k0 += 8) {
            const uint32_t a0 = Qu[ar0 + k0 + tig];
            const uint32_t a1 = Qu[ar1 + k0 + tig];
            const uint32_t a2 = Qu[ar0 + k0 + tig + 4];
            const uint32_t a3 = Qu[ar1 + k0 + tig + 4];
            #pragma unroll
            for (int nb = 0; nb < 8; nb++) {
                const int br = (nb * 8 + g) * 68 + k0 + tig;
                mma_tf32(sA[nb][0], sA[nb][1], sA[nb][2], sA[nb][3],
                         a0, a1, a2, a3, Ku[br], Ku[br + 4]);
            }
        }

        // per-row-slot online softmax (rows warp-private)
        #pragma unroll
        for (int rs = 0; rs < 2; rs++) {
            const int qrow = q0 + wrow + g + 8 * rs;
            if (k0t + 63 > qrow) {
                #pragma unroll
                for (int nb = 0; nb < 8; nb++) {
                    const int c0 = k0t + nb * 8 + 2 * tig;
                    if (c0     > qrow) sA[nb][2*rs]     = -1e30f;
                    if (c0 + 1 > qrow) sA[nb][2*rs + 1] = -1e30f;
                }
            }
            float rm = -1e30f;
            #pragma unroll
            for (int nb = 0; nb < 8; nb++)
                rm = fmaxf(rm, fmaxf(sA[nb][2*rs], sA[nb][2*rs+1]));
            rm = fmaxf(rm, __shfl_xor_sync(0xffffffffu, rm, 1));
            rm = fmaxf(rm, __shfl_xor_sync(0xffffffffu, rm, 2));
            const float mn = fmaxf(mrow[rs], rm);
            const float alpha = fast_exp2((mrow[rs] - mn) * l2s);
            mrow[rs] = mn;
            float rsum = 0.f;
            #pragma unroll
            for (int nb = 0; nb < 8; nb++) {
                float p0 = fast_exp2((sA[nb][2*rs]   - mn) * l2s);
                float p1 = fast_exp2((sA[nb][2*rs+1] - mn) * l2s);
                sA[nb][2*rs] = p0; sA[nb][2*rs+1] = p1;
                rsum += p0 + p1;
            }
            rsum += __shfl_xor_sync(0xffffffffu, rsum, 1);
            rsum += __shfl_xor_sync(0xffffffffu, rsum, 2);
            lrow[rs] = lrow[rs] * alpha + rsum;
            #pragma unroll
            for (int nb = 0; nb < 8; nb++) {
                o[nb][2*rs]   *= alpha;
                o[nb][2*rs+1] *= alpha;
            }
            const int prow = (wrow + g + 8 * rs) * 68;
            #pragma unroll
            for (int nb = 0; nb < 8; nb++) {
                uint2 pv = { f2tf32(sA[nb][2*rs]), f2tf32(sA[nb][2*rs+1]) };
                *(uint2*)&Pu[prow + nb * 8 + 2 * tig] = pv;
            }
        }
        __syncwarp();   // P STS visible within warp before A-frag reload

        // O += P V
        #pragma unroll
        for (int k0 = 0; k0 < 64; k0 += 8) {
            const uint32_t a0 = Pu[ar0 + k0 + tig];
            const uint32_t a1 = Pu[ar1 + k0 + tig];
            const uint32_t a2 = Pu[ar0 + k0 + tig + 4];
            const uint32_t a3 = Pu[ar1 + k0 + tig + 4];
            const int vb0 = (k0 + tig) * 72 + g;
            const int vb1 = (k0 + tig + 4) * 72 + g;
            #pragma unroll
            for (int nb = 0; nb < 8; nb++) {
                mma_tf32(o[nb][0], o[nb][1], o[nb][2], o[nb][3],
                         a0, a1, a2, a3, Vu[vb0 + nb * 8], Vu[vb1 + nb * 8]);
            }
        }

        // STS prefetched tile into the other buffer (read at next iter's sync)
        {
            uint32_t* Kw = Kb + ((kt + 1) & 1) * 64 * 68;
            uint32_t* Vw = Vb + ((kt + 1) & 1) * 64 * 72;
            #pragma unroll
            for (int r = 0; r < 4; r++) {
                const int row = sr0 + r * 16;
                uint4 uk = { f2tf32(rk[r].x), f2tf32(rk[r].y), f2tf32(rk[r].z), f2tf32(rk[r].w) };
                uint4 uv = { f2tf32(rv[r].x), f2tf32(rv[r].y), f2tf32(rv[r].z), f2tf32(rv[r].w) };
                *(uint4*)&Kw[row * 68 + c4 * 4] = uk;
                *(uint4*)&Vw[row * 72 + c4 * 4] = uv;
            }
        }
    }

    // normalize and store concat-heads layout
    const int b = bh >> 4, h = bh & 15;
    float* Og = g_o + ((size_t)(b * TT + q0)) * DD + h * DKK;
    #pragma unroll
    for (int rs = 0; rs < 2; rs++) {
        const float inv = 1.0f / lrow[rs];
        float* orow = Og + (size_t)(wrow + g + 8 * rs) * DD;
        #pragma unroll
        for (int nb = 0; nb < 8; nb++) {
            float2 v = { o[nb][2*rs] * inv, o[nb][2*rs+1] * inv };
            *(float2*)(orow + nb * 8 + 2 * tig) = v;
        }
    }
}

// ---------------------------------------------------------------------------
// Kernel 3: output projection y = o @ Wp^T + bp, TF32, double-buffered BK=32.
// grid = (D/128, B*T/128), 256 threads = 8 warps (4M x 2N), warp 32x64.
// Dynamic smem: 4 * 128*36 * 4 = 73,728 B
// ---------------------------------------------------------------------------
__global__ __launch_bounds__(256) void proj_kernel(
    const float* __restrict__ Wp, const float* __restrict__ bp,
    float* __restrict__ y)
{
    extern __shared__ float psm[];
    uint32_t* Ob = (uint32_t*)psm;          // [2][128*36]
    uint32_t* Wb = Ob + 2 * 128 * 36;       // [2][128*36]

    const int j0 = blockIdx.x * 128;
    const int r0 = blockIdx.y * 128;
    const int tid = threadIdx.x;
    const int wid = tid >> 5, lane = tid & 31;
    const int g = lane >> 2, tig = lane & 3;
    const int wm = wid & 3, wn = wid >> 2;
    const int c4 = tid & 7, rb = tid >> 3;

    // prologue: stage kc=0 into buffer 0
    #pragma unroll
    for (int r = 0; r < 4; r++) {
        const int row = rb + 32 * r;
        float4 vo = *(const float4*)(g_o + (size_t)(r0 + row) * DD + c4 * 4);
        float4 vw = *(const float4*)(Wp  + (size_t)(j0 + row) * DD + c4 * 4);
        uint4 uo = { f2tf32(vo.x), f2tf32(vo.y), f2tf32(vo.z), f2tf32(vo.w) };
        uint4 uw = { f2tf32(vw.x), f2tf32(vw.y), f2tf32(vw.z), f2tf32(vw.w) };
        *(uint4*)&Ob[row * 36 + c4 * 4] = uo;
        *(uint4*)&Wb[row * 36 + c4 * 4] = uw;
    }

    float acc[2][8][4];
    #pragma unroll
    for (int mf = 0; mf < 2; mf++)
        #pragma unroll
        for (int nb = 0; nb < 8; nb++)
            #pragma unroll
            for (int c = 0; c < 4; c++) acc[mf][nb][c] = 0.f;

    for (int it = 0; it < 32; it++) {
        // prefetch next k-chunk (clamped; discarded on last iter)
        const int kcn = min((it + 1) * 32, DD - 32);
        float4 ro[4], rw[4];
        #pragma unroll
        for (int r = 0; r < 4; r++) {
            const int row = rb + 32 * r;
            ro[r] = *(const float4*)(g_o + (size_t)(r0 + row) * DD + kcn + c4 * 4);
            rw[r] = *(const float4*)(Wp  + (size_t)(j0 + row) * DD + kcn + c4 * 4);
        }
        __syncthreads();
        const uint32_t* Ou = Ob + (it & 1) * 128 * 36;
        const uint32_t* Wu = Wb + (it & 1) * 128 * 36;

        #pragma unroll
        for (int k8 = 0; k8 < 4; k8++) {
            const int kk = k8 * 8;
            uint32_t a[2][4];
            #pragma unroll
            for (int mf = 0; mf < 2; mf++) {
                const int ar = (wm * 32 + mf * 16 + g) * 36 + kk + tig;
                a[mf][0] = Ou[ar];
                a[mf][1] = Ou[ar + 8 * 36];
                a[mf][2] = Ou[ar + 4];
                a[mf][3] = Ou[ar + 8 * 36 + 4];
            }
            #pragma unroll
            for (int nb = 0; nb < 8; nb++) {
                const int br = (wn * 64 + nb * 8 + g) * 36 + kk + tig;
                const uint32_t b0 = Wu[br], b1 = Wu[br + 4];
                mma_tf32(acc[0][nb][0], acc[0][nb][1], acc[0][nb][2], acc[0][nb][3],
                         a[0][0], a[0][1], a[0][2], a[0][3], b0, b1);
                mma_tf32(acc[1][nb][0], acc[1][nb][1], acc[1][nb][2], acc[1][nb][3],
                         a[1][0], a[1][1], a[1][2], a[1][3], b0, b1);
            }
        }

        // STS prefetched chunk into the other buffer
        {
            uint32_t* Ow = Ob + ((it + 1) & 1) * 128 * 36;
            uint32_t* Ww = Wb + ((it + 1) & 1) * 128 * 36;
            #pragma unroll
            for (int r = 0; r < 4; r++) {
                const int row = rb + 32 * r;
                uint4 uo = { f2tf32(ro[r].x), f2tf32(ro[r].y), f2tf32(ro[r].z), f2tf32(ro[r].w) };
                uint4 uw = { f2tf32(rw[r].x), f2tf32(rw[r].y), f2tf32(rw[r].z), f2tf32(rw[r].w) };
                *(uint4*)&Ow[row * 36 + c4 * 4] = uo;
                *(uint4*)&Ww[row * 36 + c4 * 4] = uw;
            }
        }
    }

    #pragma unroll
    for (int mf = 0; mf < 2; mf++)
        #pragma unroll
        for (int rs = 0; rs < 2; rs++) {
            const int row = r0 + wm * 32 + mf * 16 + g + 8 * rs;
            float* yr = y + (size_t)row * DD + j0 + wn * 64;
            const float* br = bp + j0 + wn * 64;
            #pragma unroll
            for (int nb = 0; nb < 8; nb++) {
                const int c = nb * 8 + 2 * tig;
                float2 v = { acc[mf][nb][2*rs]   + br[c],
                             acc[mf][nb][2*rs+1] + br[c + 1] };
                *(float2*)(yr + c) = v;
            }
        }
}

// ---------------------------------------------------------------------------
#define QKV_SMEM  ((128*68 + 3*64*68) * (int)sizeof(float))                        // 87,040
#define ATTN_SMEM ((128*68 + 2*64*68 + 2*64*72 + 128*68) * (int)sizeof(float))     // 141,312
#define PROJ_SMEM (4 * 128 * 36 * (int)sizeof(float))                              // 73,728

extern "C" void kernel_launch(void* const* d_in, const int* in_sizes, int n_in,
                              void* d_out, int out_size)
{
    const float* x  = (const float*)d_in[0];
    const float* Wq = (const float*)d_in[1];
    const float* Wk = (const float*)d_in[2];
    const float* Wv = (const float*)d_in[3];
    const float* Wp = (const float*)d_in[4];
    const float* bp = (const float*)d_in[5];
    float* y = (float*)d_out;

    cudaFuncSetAttribute(qkv_kernel,  cudaFuncAttributeMaxDynamicSharedMemorySize, QKV_SMEM);
    cudaFuncSetAttribute(attn_kernel, cudaFuncAttributeMaxDynamicSharedMemorySize, ATTN_SMEM);
    cudaFuncSetAttribute(proj_kernel, cudaFuncAttributeMaxDynamicSharedMemorySize, PROJ_SMEM);

    qkv_kernel<<<dim3(TT / 128, BH), 256, QKV_SMEM>>>(x, Wq, Wk, Wv);
    attn_kernel<<<dim3(TT / 128, BH), 256, ATTN_SMEM>>>();
    proj_kernel<<<dim3(DD / 128, (BB * TT) / 128), 256, PROJ_SMEM>>>(Wp, bp, y);
}